// round 2
// baseline (speedup 1.0000x reference)
#include <cuda_runtime.h>
#include <math.h>

#define TLEN    6000
#define NP      199
#define PLEN    60
#define PSTRIDE 30
#define NSP     30
#define NFREQ   16
#define NM      13
#define NS      9
#define NFEAT   22
#define TM      128
#define MAXROWS (1024*NP)

// 22-dim normalized feature rows (203776 x 22)
__device__ float g_F[(size_t)MAXROWS * NFEAT];

__device__ __forceinline__ float geluf(float v){
    return 0.5f * v * (1.0f + erff(v * 0.7071067811865476f));
}

// ---- packed f32x2 helpers ----
__device__ __forceinline__ unsigned long long pk2(float a, float b){
    unsigned long long r;
    asm("mov.b64 %0, {%1, %2};" : "=l"(r)
        : "r"(__float_as_uint(a)), "r"(__float_as_uint(b)));
    return r;
}
__device__ __forceinline__ unsigned long long ffma2(unsigned long long a,
                                                    unsigned long long b,
                                                    unsigned long long c){
    unsigned long long d;
    asm("fma.rn.f32x2 %0, %1, %2, %3;" : "=l"(d) : "l"(a), "l"(b), "l"(c));
    return d;
}
__device__ __forceinline__ float lo2(unsigned long long a){
    return __uint_as_float((unsigned)(a & 0xffffffffull));
}
__device__ __forceinline__ float hi2(unsigned long long a){
    return __uint_as_float((unsigned)(a >> 32));
}

__device__ __forceinline__ float freqf(int k){
    return (float)(((double)k * 200.0) / 30.0);
}

// ============================================================
// Kernel A: per-patch features + group layernorms -> g_F
// ============================================================
__global__ __launch_bounds__(256) void feat_kernel(
    const float* __restrict__ x,
    const float* __restrict__ gm, const float* __restrict__ bm,
    const float* __restrict__ gs, const float* __restrict__ bs)
{
    __shared__ float  sx[TLEN];
    __shared__ float2 tab[NFREQ * NSP];
    __shared__ float  hannS[NSP];

    const int tid = threadIdx.x;
    {
        const float4* xg = (const float4*)(x + (size_t)blockIdx.x * TLEN);
        float4* s4 = (float4*)sx;
        for (int i = tid; i < TLEN/4; i += 256) s4[i] = xg[i];
    }
    for (int i = tid; i < NFREQ*NSP; i += 256) {
        int k = i / NSP, t = i - k*NSP;
        double sv, cv;
        sincospi(2.0 * (double)(k * t) / 30.0, &sv, &cv);
        tab[i] = make_float2((float)cv, (float)sv);
    }
    if (tid < NSP)
        hannS[tid] = (float)(0.5 * (1.0 - cospi(2.0 * (double)tid / 30.0)));
    __syncthreads();
    if (tid >= NP) return;

    const int off = tid * PSTRIDE;
    float* frow = &g_F[((size_t)blockIdx.x * NP + tid) * NFEAT];

    // ---- morph pass 1 (streaming) ----
    float v0 = sx[off];
    float mx = v0, mn = v0, sum = v0;
    float sumsq = v0 * v0;
    float amax = fabsf(v0); int aidx = 0;
    float prev = v0;
    float tsg = v0 + 1e-10f;
    int   sprev = (tsg > 0.0f) - (tsg < 0.0f);
    float dmax = -INFINITY, dmin = INFINITY, dabs = 0.0f;
    int zc = 0;
    #pragma unroll
    for (int t = 1; t < PLEN; t++) {
        float v = sx[off + t];
        mx = fmaxf(mx, v); mn = fminf(mn, v);
        sum += v; sumsq = fmaf(v, v, sumsq);
        float a = fabsf(v);
        if (a > amax) { amax = a; aidx = t; }
        float d = v - prev;
        dmax = fmaxf(dmax, d); dmin = fminf(dmin, d); dabs += fabsf(d);
        float tg = v + 1e-10f;
        int sg = (tg > 0.0f) - (tg < 0.0f);
        zc += (sg != sprev);
        sprev = sg; prev = v;
    }
    float mean = sum * (1.0f/60.0f);

    // ---- morph pass 2: central moments ----
    float m2 = 0.f, m3 = 0.f, m4 = 0.f;
    #pragma unroll
    for (int t = 0; t < PLEN; t++) {
        float c = sx[off + t] - mean;
        float c2 = c * c;
        m2 += c2; m3 = fmaf(c2, c, m3); m4 = fmaf(c2, c2, m4);
    }
    m2 *= (1.0f/60.0f); m3 *= (1.0f/60.0f); m4 *= (1.0f/60.0f);
    float stdv = sqrtf(m2);

    float morph[NM];
    morph[0] = mx; morph[1] = mn; morph[2] = mx - mn; morph[3] = mean;
    morph[4] = stdv;
    morph[5] = (float)aidx * (1.0f/60.0f);
    morph[6] = dmax; morph[7] = dmin;
    morph[8] = dabs * (1.0f/59.0f);
    morph[9] = (float)zc * (1.0f/60.0f);
    morph[10] = sumsq;
    morph[11] = m4 / (m2 * m2) - 3.0f;
    morph[12] = m3 / (m2 * stdv);
    #pragma unroll
    for (int i = 0; i < NM; i++) if (!isfinite(morph[i])) morph[i] = 0.0f;

    // morph layernorm + store (free registers before Welch)
    {
        float mu = 0.f;
        #pragma unroll
        for (int i = 0; i < NM; i++) mu += morph[i];
        mu *= (1.0f/13.0f);
        float var = 0.f;
        #pragma unroll
        for (int i = 0; i < NM; i++) { float d = morph[i]-mu; var = fmaf(d,d,var); }
        var *= (1.0f/13.0f);
        float scl = rsqrtf(var + 1e-5f);
        #pragma unroll
        for (int i = 0; i < NM; i++)
            frow[i] = fmaf((morph[i]-mu)*scl, gm[i], bm[i]);
    }

    // ---- Welch: 3 segments fused in one DFT loop ----
    float y0[NSP], y1[NSP], y2[NSP];
    float s0 = 0.f, s1 = 0.f, s2 = 0.f;
    #pragma unroll
    for (int t = 0; t < NSP; t++) { y0[t] = sx[off + t];      s0 += y0[t]; }
    #pragma unroll
    for (int t = 0; t < NSP; t++) { y2[t] = sx[off + 30 + t]; s2 += y2[t]; }
    #pragma unroll
    for (int t = 0; t < NSP; t++) { y1[t] = (t < 15) ? y0[t+15] : y2[t-15]; s1 += y1[t]; }
    s0 *= (1.0f/30.0f); s1 *= (1.0f/30.0f); s2 *= (1.0f/30.0f);
    #pragma unroll
    for (int t = 0; t < NSP; t++) {
        float w = hannS[t];
        y0[t] = (y0[t] - s0) * w;
        y1[t] = (y1[t] - s1) * w;
        y2[t] = (y2[t] - s2) * w;
    }
    float psd[NFREQ];
    for (int k = 0; k < NFREQ; k++) {
        const float2* tk = &tab[k * NSP];
        float re0=0.f, im0=0.f, re1=0.f, im1=0.f, re2=0.f, im2=0.f;
        #pragma unroll
        for (int t = 0; t < NSP; t++) {
            float2 cs = tk[t];
            re0 = fmaf(y0[t], cs.x, re0); im0 = fmaf(y0[t], cs.y, im0);
            re1 = fmaf(y1[t], cs.x, re1); im1 = fmaf(y1[t], cs.y, im1);
            re2 = fmaf(y2[t], cs.x, re2); im2 = fmaf(y2[t], cs.y, im2);
        }
        float p = fmaf(re0,re0,im0*im0) + fmaf(re1,re1,im1*im1) + fmaf(re2,re2,im2*im2);
        float sc = (k == 0 || k == NFREQ-1) ? (1.0f/6750.0f) : (2.0f/6750.0f);
        psd[k] = p * sc;
    }

    // ---- spectral features ----
    float total = 0.f;
    #pragma unroll
    for (int k = 0; k < NFREQ; k++) total += psd[k];
    total += 1e-12f;
    float inv = 1.0f / total;

    float b1v = psd[1];
    float b3v = psd[2] + psd[3] + psd[4];
    float b4v = 0.f;
    #pragma unroll
    for (int k = 5; k <= 14; k++) b4v += psd[k];

    float pmax = psd[0]; int pkk = 0;
    #pragma unroll
    for (int k = 1; k < NFREQ; k++)
        if (psd[k] > pmax) { pmax = psd[k]; pkk = k; }

    float thr = 0.95f * total;
    float csum = 0.f; int ek = 0; bool fnd = false;
    #pragma unroll
    for (int k = 0; k < NFREQ; k++) {
        csum += psd[k];
        if (!fnd && csum >= thr) { ek = k; fnd = true; }
    }
    float ent = 0.f;
    #pragma unroll
    for (int k = 0; k < NFREQ; k++) {
        float pn = psd[k] * inv;
        ent -= pn * log2f(pn + 1e-12f);
    }

    float spec[NS];
    spec[0] = 0.0f;            // (1,4): no bins
    spec[1] = b1v * inv;       // (4,8): bin 1
    spec[2] = 0.0f;            // (8,13): no bins
    spec[3] = b3v * inv;       // (13,30): bins 2..4
    spec[4] = b4v * inv;       // (30,99): bins 5..14
    spec[5] = freqf(pkk);
    spec[6] = freqf(ek);
    spec[7] = ent;
    spec[8] = total;
    #pragma unroll
    for (int i = 0; i < NS; i++) if (!isfinite(spec[i])) spec[i] = 0.0f;

    {
        float mu = 0.f;
        #pragma unroll
        for (int i = 0; i < NS; i++) mu += spec[i];
        mu *= (1.0f/9.0f);
        float var = 0.f;
        #pragma unroll
        for (int i = 0; i < NS; i++) { float d = spec[i]-mu; var = fmaf(d,d,var); }
        var *= (1.0f/9.0f);
        float scl = rsqrtf(var + 1e-5f);
        #pragma unroll
        for (int i = 0; i < NS; i++)
            frow[NM + i] = fmaf((spec[i]-mu)*scl, gs[i], bs[i]);
    }
}

// ============================================================
// Kernel B: persistent MLP  (22 -> 128 GELU -> 256 -> LN)
// ============================================================
#define SMEM_FLOATS (32768 + 16384 + 2816 + 2816 + 128 + 256 + 256 + 256)

__global__ __launch_bounds__(512, 1) void mlp_kernel(
    const float* __restrict__ W1, const float* __restrict__ b1,
    const float* __restrict__ W2, const float* __restrict__ b2,
    const float* __restrict__ go, const float* __restrict__ bo,
    float* __restrict__ out, int nRows)
{
    extern __shared__ float sm[];
    float* W2s = sm;                   // 128*256
    float* hs  = W2s + 32768;          // 128*128  h[row*128+col]
    float* Fs  = hs + 16384;           // 128*22
    float* W1s = Fs + 2816;            // 22*128
    float* b1s = W1s + 2816;           // 128
    float* b2s = b1s + 128;            // 256
    float* gos = b2s + 256;            // 256
    float* bos = gos + 256;            // 256

    const int tid = threadIdx.x;
    for (int i = tid; i < 8192; i += 512) ((float4*)W2s)[i] = ((const float4*)W2)[i];
    for (int i = tid; i < 2816; i += 512) W1s[i] = W1[i];
    if (tid < 128) b1s[tid] = b1[tid];
    for (int i = tid; i < 256; i += 512) { b2s[i]=b2[i]; gos[i]=go[i]; bos[i]=bo[i]; }

    const int rowg = tid >> 5;          // 0..15 (== warp id)
    const int lane = tid & 31;
    const int r0 = rowg * 8;
    const int c1 = lane * 4;            // GEMM1: 4 cols
    const int c2 = lane * 8;            // GEMM2: 8 cols
    const int nTiles = (nRows + TM - 1) / TM;

    for (int tile = blockIdx.x; tile < nTiles; tile += gridDim.x) {
        __syncthreads();   // protect hs/Fs from previous iteration readers
        const int rowBase = tile * TM;
        for (int i = tid; i < TM*NFEAT; i += 512) {
            int r = i / NFEAT;
            Fs[i] = (rowBase + r < nRows) ? g_F[(size_t)rowBase*NFEAT + i] : 0.0f;
        }
        __syncthreads();

        // GEMM1 + bias + exact GELU -> hs[row][col]
        {
            float acc[8][4];
            #pragma unroll
            for (int i = 0; i < 8; i++)
                #pragma unroll
                for (int j = 0; j < 4; j++) acc[i][j] = 0.0f;
            #pragma unroll
            for (int k = 0; k < NFEAT; k++) {
                float4 w = *(const float4*)&W1s[k*128 + c1];
                #pragma unroll
                for (int i = 0; i < 8; i++) {
                    float a = Fs[(r0+i)*NFEAT + k];
                    acc[i][0] = fmaf(a, w.x, acc[i][0]);
                    acc[i][1] = fmaf(a, w.y, acc[i][1]);
                    acc[i][2] = fmaf(a, w.z, acc[i][2]);
                    acc[i][3] = fmaf(a, w.w, acc[i][3]);
                }
            }
            float bx = b1s[c1+0], by = b1s[c1+1], bz = b1s[c1+2], bw = b1s[c1+3];
            #pragma unroll
            for (int i = 0; i < 8; i++) {
                float4 hv;
                hv.x = geluf(acc[i][0] + bx);
                hv.y = geluf(acc[i][1] + by);
                hv.z = geluf(acc[i][2] + bz);
                hv.w = geluf(acc[i][3] + bw);
                *(float4*)&hs[(r0+i)*128 + c1] = hv;
            }
        }
        __syncthreads();

        // GEMM2: 8 rows x 8 cols per thread, f32x2 over column pairs
        unsigned long long acc2[8][4];
        #pragma unroll
        for (int i = 0; i < 8; i++)
            #pragma unroll
            for (int j = 0; j < 4; j++) acc2[i][j] = 0ull;

        #pragma unroll 4
        for (int k = 0; k < 128; k++) {
            ulonglong2 wA = *(const ulonglong2*)&W2s[k*256 + c2];
            ulonglong2 wB = *(const ulonglong2*)&W2s[k*256 + c2 + 4];
            #pragma unroll
            for (int i = 0; i < 8; i++) {
                float av = hs[(r0+i)*128 + k];
                unsigned long long a2 = pk2(av, av);
                acc2[i][0] = ffma2(a2, wA.x, acc2[i][0]);
                acc2[i][1] = ffma2(a2, wA.y, acc2[i][1]);
                acc2[i][2] = ffma2(a2, wB.x, acc2[i][2]);
                acc2[i][3] = ffma2(a2, wB.y, acc2[i][3]);
            }
        }

        // epilogue: +b2, per-row LayerNorm over 256 (warp = one row group)
        float bb[8], gg[8], oo[8];
        #pragma unroll
        for (int j = 0; j < 8; j++) {
            bb[j] = b2s[c2+j]; gg[j] = gos[c2+j]; oo[j] = bos[c2+j];
        }
        #pragma unroll
        for (int i = 0; i < 8; i++) {
            float v[8];
            #pragma unroll
            for (int j = 0; j < 4; j++) {
                v[2*j]   = lo2(acc2[i][j]) + bb[2*j];
                v[2*j+1] = hi2(acc2[i][j]) + bb[2*j+1];
            }
            float s = 0.f;
            #pragma unroll
            for (int j = 0; j < 8; j++) s += v[j];
            #pragma unroll
            for (int off = 16; off >= 1; off >>= 1)
                s += __shfl_xor_sync(0xffffffffu, s, off);
            float mu = s * (1.0f/256.0f);
            float q = 0.f;
            #pragma unroll
            for (int j = 0; j < 8; j++) { float d = v[j]-mu; q = fmaf(d,d,q); }
            #pragma unroll
            for (int off = 16; off >= 1; off >>= 1)
                q += __shfl_xor_sync(0xffffffffu, q, off);
            float rs = rsqrtf(q * (1.0f/256.0f) + 1e-5f);

            int row = rowBase + r0 + i;
            if (row < nRows) {
                float4 o1, o2;
                o1.x = fmaf((v[0]-mu)*rs, gg[0], oo[0]);
                o1.y = fmaf((v[1]-mu)*rs, gg[1], oo[1]);
                o1.z = fmaf((v[2]-mu)*rs, gg[2], oo[2]);
                o1.w = fmaf((v[3]-mu)*rs, gg[3], oo[3]);
                o2.x = fmaf((v[4]-mu)*rs, gg[4], oo[4]);
                o2.y = fmaf((v[5]-mu)*rs, gg[5], oo[5]);
                o2.z = fmaf((v[6]-mu)*rs, gg[6], oo[6]);
                o2.w = fmaf((v[7]-mu)*rs, gg[7], oo[7]);
                float* op = &out[(size_t)row*256 + c2];
                *(float4*)op = o1;
                *(float4*)(op+4) = o2;
            }
        }
    }
}

extern "C" void kernel_launch(void* const* d_in, const int* in_sizes, int n_in,
                              void* d_out, int out_size) {
    const float* x  = (const float*)d_in[0];
    const float* gm = (const float*)d_in[1];
    const float* bm = (const float*)d_in[2];
    const float* gs = (const float*)d_in[3];
    const float* bs = (const float*)d_in[4];
    const float* W1 = (const float*)d_in[5];
    const float* b1 = (const float*)d_in[6];
    const float* W2 = (const float*)d_in[7];
    const float* b2 = (const float*)d_in[8];
    const float* go = (const float*)d_in[9];
    const float* bo = (const float*)d_in[10];

    int B = in_sizes[0] / TLEN;
    int nRows = B * NP;

    cudaFuncSetAttribute(mlp_kernel, cudaFuncAttributeMaxDynamicSharedMemorySize,
                         SMEM_FLOATS * (int)sizeof(float));

    feat_kernel<<<B, 256>>>(x, gm, bm, gs, bs);
    mlp_kernel<<<148, 512, SMEM_FLOATS * (int)sizeof(float)>>>(
        W1, b1, W2, b2, go, bo, (float*)d_out, nRows);
}